// round 1
// baseline (speedup 1.0000x reference)
#include <cuda_runtime.h>
#include <cstdint>

#define BS   16
#define MGT  256
#define NC   80
#define NA   3
#define S0   160
#define S1   80
#define S2   40
#define NG0  25600
#define NG1  6400
#define NG2  1600
#define NGT  33600
#define OFF1 25600
#define OFF2 32000

// Output float offsets (row-major flatten of the 5-tuple, all float32)
#define BASE_TXY 0ull
#define BASE_WH  3225600ull
#define BASE_SC  6451200ull
#define BASE_ANC 135475200ull
#define BASE_MSK 138700800ull
#define N_SC4    32256000    // 129,024,000 floats / 4

// Scratch (no allocations allowed)
__device__ __align__(16) int g_count[BS * NGT];
__device__ int g_claim[BS * NGT];
__device__ int g_topk[3 * BS * MGT * 3];   // global cell index of each gt's top-3, per layer
__device__ int g_lab[BS * NGT];
__device__ int g_is64;

// ---------------------------------------------------------------------------
__global__ void zero_kernel() {
    int i = blockIdx.x * blockDim.x + threadIdx.x;
    int4* p = (int4*)g_count;
    if (i < BS * NGT / 4) p[i] = make_int4(0, 0, 0, 0);
}

// Detect whether gt_labels arrived as int64 (odd int32 words all zero) or int32.
__global__ void detect_kernel(const int* __restrict__ lab32) {
    __shared__ int acc;
    if (threadIdx.x == 0) acc = 0;
    __syncthreads();
    int v = 0;
    for (int t = threadIdx.x; t < 2048; t += blockDim.x)
        v |= lab32[2 * t + 1];
    if (v) atomicOr(&acc, 1);
    __syncthreads();
    if (threadIdx.x == 0) g_is64 = (acc == 0) ? 1 : 0;
}

// ---------------------------------------------------------------------------
// One thread per (layer, b, m): analytic top-3 nearest cells + claim scatter.
__global__ void claim_kernel(const float* __restrict__ gt_cxy,
                             const float* __restrict__ mask_gt,
                             const float* __restrict__ strides) {
    int idx = blockIdx.x * blockDim.x + threadIdx.x;
    if (idx >= 3 * BS * MGT) return;
    int l  = idx / (BS * MGT);
    int bm = idx - l * (BS * MGT);
    int b  = bm / MGT;
    int m  = bm - b * MGT;

    int s   = (l == 0) ? S0 : (l == 1) ? S1 : S2;
    int off = (l == 0) ? 0  : (l == 1) ? OFF1 : OFF2;
    float stride = strides[l];

    float gcx = __fdiv_rn(gt_cxy[2 * bm], stride);
    float gcy = __fdiv_rn(gt_cxy[2 * bm + 1], stride);

    int x0 = (int)floorf(gcx); x0 = min(max(x0, 0), s - 1);
    int y0 = (int)floorf(gcy); y0 = min(max(y0, 0), s - 1);
    int xs = max(0, x0 - 2), xe = min(s - 1, x0 + 2);
    int ys = max(0, y0 - 2), ye = min(s - 1, y0 + 2);

    float d0 = 1e30f, d1 = 1e30f, d2 = 1e30f;
    int   i0 = 0,     i1 = 0,     i2 = 0;
    for (int yy = ys; yy <= ye; yy++) {
        float ady = fabsf((float)yy + 0.5f - gcy);
        for (int xx = xs; xx <= xe; xx++) {
            float d = fabsf((float)xx + 0.5f - gcx) + ady;
            int gi = yy * s + xx;
            // strict < keeps the smaller-index cell on exact ties (top_k stability)
            if (d < d0)      { d2 = d1; i2 = i1; d1 = d0; i1 = i0; d0 = d; i0 = gi; }
            else if (d < d1) { d2 = d1; i2 = i1; d1 = d;  i1 = gi; }
            else if (d < d2) { d2 = d;  i2 = gi; }
        }
    }
    int gA = off + i0, gB = off + i1, gC = off + i2;
    int* tk = g_topk + (((l * BS) + b) * MGT + m) * 3;
    tk[0] = gA; tk[1] = gB; tk[2] = gC;

    if (mask_gt[bm] != 0.0f) {
        atomicAdd(&g_count[b * NGT + gA], 1); g_claim[b * NGT + gA] = m;
        atomicAdd(&g_count[b * NGT + gB], 1); g_claim[b * NGT + gB] = m;
        atomicAdd(&g_count[b * NGT + gC], 1); g_claim[b * NGT + gC] = m;
    }
}

// ---------------------------------------------------------------------------
// One thread per (b, cell): conflict resolution + all outputs except scores.
__global__ __launch_bounds__(256)
void resolve_kernel(const float* __restrict__ gt_cxy,
                    const float* __restrict__ gt_wh,
                    const int*   __restrict__ lab32,
                    const float* __restrict__ mask_gt,
                    const float* __restrict__ strides,
                    const float* __restrict__ anc_whs,
                    float* __restrict__ out) {
    int idx = blockIdx.x * blockDim.x + threadIdx.x;
    if (idx >= BS * NGT) return;
    int b  = idx / NGT;
    int gg = idx - b * NGT;

    int l, s, off;
    if (gg < OFF1)      { l = 0; s = S0; off = 0;    }
    else if (gg < OFF2) { l = 1; s = S1; off = OFF1; }
    else                { l = 2; s = S2; off = OFF2; }
    int lg = gg - off;
    int gx = lg % s;
    int gy = lg / s;
    float stride = strides[l];

    int c   = g_count[idx];
    int tgt = 0, fgv = 0;
    if (c == 1) {
        tgt = g_claim[idx];
        fgv = 1;
    } else if (c > 1) {
        // argmax_m metric (first max wins), membership check against that gt's top-3
        float cx = (float)gx + 0.5f, cy = (float)gy + 0.5f;
        float best = -1.0f; int mmax = 0;
        const float* p = gt_cxy + (size_t)b * MGT * 2;
        for (int m = 0; m < MGT; m++) {
            float gcx = __fdiv_rn(p[2 * m],     stride);
            float gcy = __fdiv_rn(p[2 * m + 1], stride);
            float d = fabsf(cx - gcx) + fabsf(cy - gcy);
            if (d > best) { best = d; mmax = m; }
        }
        const int* tk = g_topk + (((l * BS) + b) * MGT + mmax) * 3;
        bool claimed = (mask_gt[b * MGT + mmax] != 0.0f) &&
                       (tk[0] == gg || tk[1] == gg || tk[2] == gg);
        if (claimed) { tgt = mmax; fgv = 1; }
    }

    int gi = b * MGT + tgt;
    float tx = __fdiv_rn(gt_cxy[2 * gi],     stride) - (float)gx;
    float ty = __fdiv_rn(gt_cxy[2 * gi + 1], stride) - (float)gy;
    float tw = __fdiv_rn(gt_wh[2 * gi],      stride);
    float th = __fdiv_rn(gt_wh[2 * gi + 1],  stride);
    int lab = g_is64 ? lab32[2 * gi] : lab32[gi];
    g_lab[idx] = lab;

    float2* out_txy = (float2*)(out + BASE_TXY);
    float2* out_wh  = (float2*)(out + BASE_WH);
    float2* out_anc = (float2*)(out + BASE_ANC);
    float*  out_msk = out + BASE_MSK;

    #pragma unroll
    for (int j = 0; j < NA; j++) {
        size_t o = ((size_t)(b * NA + j)) * NGT + gg;
        out_txy[o] = make_float2(tx, ty);
        out_wh[o]  = make_float2(tw, th);
        float aw = __fdiv_rn(anc_whs[(l * NA + j) * 2],     stride);
        float ah = __fdiv_rn(anc_whs[(l * NA + j) * 2 + 1], stride);
        out_anc[o] = make_float2(aw, ah);
        float rw = __fdiv_rn(tw, aw);
        float rh = __fdiv_rn(th, ah);
        float mr = fmaxf(fmaxf(rw, __fdiv_rn(1.0f, rw)),
                         fmaxf(rh, __fdiv_rn(1.0f, rh)));
        out_msk[o] = (fgv && mr < 4.0f) ? 1.0f : 0.0f;
    }
}

// ---------------------------------------------------------------------------
// One float4 per thread: fully coalesced 516 MB one-hot scores stream.
__global__ __launch_bounds__(256)
void scores_kernel(float* __restrict__ out) {
    int t = blockIdx.x * blockDim.x + threadIdx.x;
    if (t >= N_SC4) return;
    int c4 = t % 20;
    int r  = t / 20;
    int g  = r % NGT;
    int b  = (r / NGT) / NA;
    int lab = g_lab[b * NGT + g];
    int base = c4 * 4;
    float4 v;
    v.x = (lab == base)     ? 1.0f : 0.0f;
    v.y = (lab == base + 1) ? 1.0f : 0.0f;
    v.z = (lab == base + 2) ? 1.0f : 0.0f;
    v.w = (lab == base + 3) ? 1.0f : 0.0f;
    ((float4*)(out + BASE_SC))[t] = v;
}

// ---------------------------------------------------------------------------
extern "C" void kernel_launch(void* const* d_in, const int* in_sizes, int n_in,
                              void* d_out, int out_size) {
    const float* anc     = (const float*)d_in[0];
    // d_in[1..3] = grids (recomputed analytically, unused)
    const int*   lab32   = (const int*)d_in[4];
    const float* gt_cxy  = (const float*)d_in[5];
    const float* gt_wh   = (const float*)d_in[6];
    const float* strides = (const float*)d_in[7];
    const float* mask_gt = (const float*)d_in[8];
    float* out = (float*)d_out;

    zero_kernel<<<(BS * NGT / 4 + 255) / 256, 256>>>();
    detect_kernel<<<1, 256>>>(lab32);
    claim_kernel<<<(3 * BS * MGT + 255) / 256, 256>>>(gt_cxy, mask_gt, strides);
    resolve_kernel<<<(BS * NGT + 255) / 256, 256>>>(gt_cxy, gt_wh, lab32, mask_gt,
                                                    strides, anc, out);
    scores_kernel<<<(N_SC4 + 255) / 256, 256>>>(out);
}

// round 2
// speedup vs baseline: 1.0845x; 1.0845x over previous
#include <cuda_runtime.h>
#include <cstdint>

#define BS   16
#define MGT  256
#define NC   80
#define NA   3
#define S0   160
#define S1   80
#define S2   40
#define NGT  33600
#define OFF1 25600
#define OFF2 32000

// Output float offsets (row-major flatten of the 5-tuple, all float32)
#define BASE_TXY 0ull
#define BASE_WH  3225600ull
#define BASE_SC  6451200ull
#define BASE_ANC 135475200ull
#define BASE_MSK 138700800ull
#define N_SC4    32256000    // 129,024,000 floats / 4

// Scratch (no allocations allowed)
__device__ __align__(16) int g_count[BS * NGT];
__device__ int   g_claim[BS * NGT];
__device__ int   g_topk[3 * BS * MGT * 3];     // global cell idx of each gt's top-3
__device__ float g_gcxy[3 * BS * MGT * 2];     // gt_cxy / stride, per layer
__device__ float g_gwh [3 * BS * MGT * 2];     // gt_wh  / stride, per layer
__device__ int   g_amask[3 * BS * MGT];        // 3-bit anchor wh-ratio gate per (l,gt)
__device__ int   g_labn[BS * MGT];             // normalized int32 labels
__device__ int   g_lab3[BS * NA * NGT];        // per-row label for scores kernel
__device__ float g_ancs[9 * 2];                // anc_wh / stride
__device__ int   g_is64;

// ---------------------------------------------------------------------------
__global__ void zero_kernel() {
    int i = blockIdx.x * blockDim.x + threadIdx.x;
    int4* p = (int4*)g_count;
    if (i < BS * NGT / 4) p[i] = make_int4(0, 0, 0, 0);
}

// Detect int64-vs-int32 labels; precompute anchor/stride table.
__global__ void detect_kernel(const int* __restrict__ lab32,
                              const float* __restrict__ anc_whs,
                              const float* __restrict__ strides) {
    __shared__ int acc;
    if (threadIdx.x == 0) acc = 0;
    __syncthreads();
    int v = 0;
    for (int t = threadIdx.x; t < BS * MGT; t += blockDim.x)
        v |= lab32[2 * t + 1];
    if (v) atomicOr(&acc, 1);
    __syncthreads();
    if (threadIdx.x == 0) g_is64 = (acc == 0) ? 1 : 0;
    if (threadIdx.x < 9) {
        float st = strides[threadIdx.x / 3];
        g_ancs[2 * threadIdx.x]     = __fdiv_rn(anc_whs[2 * threadIdx.x],     st);
        g_ancs[2 * threadIdx.x + 1] = __fdiv_rn(anc_whs[2 * threadIdx.x + 1], st);
    }
}

// ---------------------------------------------------------------------------
// One thread per (layer, b, m): all per-gt precompute + top-3 claim scatter.
__global__ void claim_kernel(const float* __restrict__ gt_cxy,
                             const float* __restrict__ gt_wh,
                             const int*   __restrict__ lab32,
                             const float* __restrict__ mask_gt,
                             const float* __restrict__ strides) {
    int idx = blockIdx.x * blockDim.x + threadIdx.x;
    if (idx >= 3 * BS * MGT) return;
    int l  = idx / (BS * MGT);
    int bm = idx - l * (BS * MGT);
    int b  = bm / MGT;

    int s   = (l == 0) ? S0 : (l == 1) ? S1 : S2;
    int off = (l == 0) ? 0  : (l == 1) ? OFF1 : OFF2;
    float stride = strides[l];

    // normalized labels (layer-0 threads cover all (b,m) once)
    if (l == 0)
        g_labn[bm] = g_is64 ? lab32[2 * bm] : lab32[bm];

    float gcx = __fdiv_rn(gt_cxy[2 * bm],     stride);
    float gcy = __fdiv_rn(gt_cxy[2 * bm + 1], stride);
    g_gcxy[2 * idx]     = gcx;
    g_gcxy[2 * idx + 1] = gcy;

    float tw = __fdiv_rn(gt_wh[2 * bm],     stride);
    float th = __fdiv_rn(gt_wh[2 * bm + 1], stride);
    g_gwh[2 * idx]     = tw;
    g_gwh[2 * idx + 1] = th;

    // per-anchor wh-ratio gate (cell independent): max(r,1/r).max(-1) < 4
    int amask = 0;
    #pragma unroll
    for (int j = 0; j < NA; j++) {
        float aw = g_ancs[(l * NA + j) * 2];
        float ah = g_ancs[(l * NA + j) * 2 + 1];
        float rw = __fdiv_rn(tw, aw);
        float rh = __fdiv_rn(th, ah);
        float mr = fmaxf(fmaxf(rw, __fdiv_rn(1.0f, rw)),
                         fmaxf(rh, __fdiv_rn(1.0f, rh)));
        if (mr < 4.0f) amask |= (1 << j);
    }
    g_amask[idx] = amask;

    // analytic top-3 nearest cells: 5x5 window around floor(gcxy)
    int x0 = (int)floorf(gcx); x0 = min(max(x0, 0), s - 1);
    int y0 = (int)floorf(gcy); y0 = min(max(y0, 0), s - 1);
    int xs = max(0, x0 - 2), xe = min(s - 1, x0 + 2);
    int ys = max(0, y0 - 2), ye = min(s - 1, y0 + 2);

    float d0 = 1e30f, d1 = 1e30f, d2 = 1e30f;
    int   i0 = 0,     i1 = 0,     i2 = 0;
    for (int yy = ys; yy <= ye; yy++) {
        float ady = fabsf((float)yy + 0.5f - gcy);
        for (int xx = xs; xx <= xe; xx++) {
            float d = fabsf((float)xx + 0.5f - gcx) + ady;
            int gi = yy * s + xx;
            if (d < d0)      { d2 = d1; i2 = i1; d1 = d0; i1 = i0; d0 = d; i0 = gi; }
            else if (d < d1) { d2 = d1; i2 = i1; d1 = d;  i1 = gi; }
            else if (d < d2) { d2 = d;  i2 = gi; }
        }
    }
    int gA = off + i0, gB = off + i1, gC = off + i2;
    int* tk = g_topk + (((l * BS) + b) * MGT + (bm - b * MGT)) * 3;
    tk[0] = gA; tk[1] = gB; tk[2] = gC;

    if (mask_gt[bm] != 0.0f) {
        int m = bm - b * MGT;
        atomicAdd(&g_count[b * NGT + gA], 1); g_claim[b * NGT + gA] = m;
        atomicAdd(&g_count[b * NGT + gB], 1); g_claim[b * NGT + gB] = m;
        atomicAdd(&g_count[b * NGT + gC], 1); g_claim[b * NGT + gC] = m;
    }
}

// ---------------------------------------------------------------------------
// One thread per (b, cell): divide-free resolution + all outputs but scores.
__global__ __launch_bounds__(256)
void resolve_kernel(const float* __restrict__ mask_gt,
                    float* __restrict__ out) {
    int idx = blockIdx.x * blockDim.x + threadIdx.x;
    if (idx >= BS * NGT) return;
    int b  = idx / NGT;
    int gg = idx - b * NGT;

    int l, s, off;
    if (gg < OFF1)      { l = 0; s = S0; off = 0;    }
    else if (gg < OFF2) { l = 1; s = S1; off = OFF1; }
    else                { l = 2; s = S2; off = OFF2; }
    int lg = gg - off;
    int gx = lg % s;
    int gy = lg / s;

    int lb = (l * BS + b) * MGT;                 // base gt index for (l,b)
    const float2* gcxy = (const float2*)g_gcxy + lb;

    int c   = g_count[idx];
    int tgt = 0, fgv = 0;
    if (c == 1) {
        tgt = g_claim[idx];
        fgv = 1;
    } else if (c > 1) {
        // argmax_m metric (first max wins, strict >), then top-3 membership
        float cx = (float)gx + 0.5f, cy = (float)gy + 0.5f;
        float best = -1.0f; int mmax = 0;
        for (int m = 0; m < MGT; m++) {
            float2 gc = __ldg(&gcxy[m]);
            float d = fabsf(cx - gc.x) + fabsf(cy - gc.y);
            if (d > best) { best = d; mmax = m; }
        }
        const int* tk = g_topk + (lb + mmax) * 3;
        bool claimed = (mask_gt[b * MGT + mmax] != 0.0f) &&
                       (tk[0] == gg || tk[1] == gg || tk[2] == gg);
        if (claimed) { tgt = mmax; fgv = 1; }
    }

    float2 tcxy = __ldg(&gcxy[tgt]);
    float2 twh  = __ldg(&((const float2*)g_gwh)[lb + tgt]);
    int lab     = g_labn[b * MGT + tgt];
    int amask   = g_amask[lb + tgt];
    float tx = tcxy.x - (float)gx;
    float ty = tcxy.y - (float)gy;

    float2* out_txy = (float2*)(out + BASE_TXY);
    float2* out_wh  = (float2*)(out + BASE_WH);
    float2* out_anc = (float2*)(out + BASE_ANC);
    float*  out_msk = out + BASE_MSK;

    #pragma unroll
    for (int j = 0; j < NA; j++) {
        size_t o = ((size_t)(b * NA + j)) * NGT + gg;
        out_txy[o] = make_float2(tx, ty);
        out_wh[o]  = twh;
        out_anc[o] = ((const float2*)g_ancs)[l * NA + j];
        out_msk[o] = (fgv && ((amask >> j) & 1)) ? 1.0f : 0.0f;
        g_lab3[o]  = lab;
    }
}

// ---------------------------------------------------------------------------
// One float4 per thread: fully coalesced 516 MB one-hot scores stream.
__global__ __launch_bounds__(256)
void scores_kernel(float* __restrict__ out) {
    int t = blockIdx.x * blockDim.x + threadIdx.x;
    if (t >= N_SC4) return;
    int c4  = t % 20;
    int row = t / 20;
    int lab = g_lab3[row];
    int base = c4 * 4;
    float4 v;
    v.x = (lab == base)     ? 1.0f : 0.0f;
    v.y = (lab == base + 1) ? 1.0f : 0.0f;
    v.z = (lab == base + 2) ? 1.0f : 0.0f;
    v.w = (lab == base + 3) ? 1.0f : 0.0f;
    ((float4*)(out + BASE_SC))[t] = v;
}

// ---------------------------------------------------------------------------
extern "C" void kernel_launch(void* const* d_in, const int* in_sizes, int n_in,
                              void* d_out, int out_size) {
    const float* anc     = (const float*)d_in[0];
    // d_in[1..3] = grids (recomputed analytically, unused)
    const int*   lab32   = (const int*)d_in[4];
    const float* gt_cxy  = (const float*)d_in[5];
    const float* gt_wh   = (const float*)d_in[6];
    const float* strides = (const float*)d_in[7];
    const float* mask_gt = (const float*)d_in[8];
    float* out = (float*)d_out;

    zero_kernel<<<(BS * NGT / 4 + 255) / 256, 256>>>();
    detect_kernel<<<1, 256>>>(lab32, anc, strides);
    claim_kernel<<<(3 * BS * MGT + 255) / 256, 256>>>(gt_cxy, gt_wh, lab32,
                                                      mask_gt, strides);
    resolve_kernel<<<(BS * NGT + 255) / 256, 256>>>(mask_gt, out);
    scores_kernel<<<(N_SC4 + 255) / 256, 256>>>(out);
}